// round 3
// baseline (speedup 1.0000x reference)
#include <cuda_runtime.h>

#define D        32000
#define NV4      (D / 4)
#define THREADS  1024
#define NWARP    (THREADS / 32)
#define CCAP     6144
#define SMEM_BYTES (D * 4 + CCAP * 4)

__device__ __forceinline__ float warpSum(float v) {
#pragma unroll
    for (int o = 16; o > 0; o >>= 1) v += __shfl_down_sync(0xffffffffu, v, o);
    return v;
}
__device__ __forceinline__ float warpMax(float v) {
#pragma unroll
    for (int o = 16; o > 0; o >>= 1) v = fmaxf(v, __shfl_down_sync(0xffffffffu, v, o));
    return v;
}

struct Red {
    float red[NWARP][4];
    float bcast[4];
    int   cnt;
};

// Block-reduce 4 partial sums; results broadcast via r->bcast[0..3].
__device__ void reduce4(float s0, float s1, float s2, float s3,
                        Red* r, int lane, int wid) {
    s0 = warpSum(s0); s1 = warpSum(s1); s2 = warpSum(s2); s3 = warpSum(s3);
    if (lane == 0) {
        r->red[wid][0] = s0; r->red[wid][1] = s1;
        r->red[wid][2] = s2; r->red[wid][3] = s3;
    }
    __syncthreads();
    if (wid == 0) {
        float a = r->red[lane][0], b = r->red[lane][1];
        float c = r->red[lane][2], d = r->red[lane][3];
        a = warpSum(a); b = warpSum(b); c = warpSum(c); d = warpSum(d);
        if (lane == 0) {
            r->bcast[0] = a; r->bcast[1] = b; r->bcast[2] = c; r->bcast[3] = d;
        }
    }
    __syncthreads();
}

// Evaluate mass at the 4 interior probes over the FULL row (SMEM resident).
__device__ void mass4_full(const float* xs, float tau_lo, float width,
                           Red* r, int tid, int lane, int wid) {
    const float t1 = tau_lo + 1.0f * width;
    const float t2 = tau_lo + 2.0f * width;
    const float t3 = tau_lo + 3.0f * width;
    const float t4 = tau_lo + 4.0f * width;
    float s0 = 0.f, s1 = 0.f, s2 = 0.f, s3 = 0.f;
    const float4* x4 = (const float4*)xs;
    for (int k = tid; k < NV4; k += THREADS) {
        float4 v = x4[k];
#define ACC(c)                                                   \
        {                                                        \
            float d0 = fmaxf((c) - t1, 0.f); s0 = fmaf(d0, d0, s0); \
            float d1 = fmaxf((c) - t2, 0.f); s1 = fmaf(d1, d1, s1); \
            float d2 = fmaxf((c) - t3, 0.f); s2 = fmaf(d2, d2, s2); \
            float d3 = fmaxf((c) - t4, 0.f); s3 = fmaf(d3, d3, s3); \
        }
        ACC(v.x) ACC(v.y) ACC(v.z) ACC(v.w)
#undef ACC
    }
    reduce4(s0, s1, s2, s3, r, lane, wid);
}

__device__ __forceinline__ void update_tau(float& tau_lo, float& tau_hi,
                                           float width, const Red* r) {
    // j_best = largest j in 1..4 with mass >= 1 (reference semantics)
    int jb = 0;
    if (r->bcast[0] >= 1.0f) jb = 1;
    if (r->bcast[1] >= 1.0f) jb = 2;
    if (r->bcast[2] >= 1.0f) jb = 3;
    if (r->bcast[3] >= 1.0f) jb = 4;
    tau_lo = tau_lo + (float)jb * width;
    tau_hi = tau_lo + width;
}

__global__ __launch_bounds__(THREADS, 1)
void entmax_kernel(const float* __restrict__ X, float* __restrict__ Y) {
    extern __shared__ float smem[];
    float* xs    = smem;          // D floats: Xs = 0.5*x
    float* cvals = smem + D;      // CCAP floats: compacted active values

    __shared__ Red r;

    const int tid  = threadIdx.x;
    const int lane = tid & 31;
    const int wid  = tid >> 5;
    const size_t rowoff = (size_t)blockIdx.x * D;
    const float4* __restrict__ xin  = (const float4*)(X + rowoff);
    float4* __restrict__       yout = (float4*)(Y + rowoff);

    // ---- Pass A: load from HBM, scale by (alpha-1)=0.5, cache in SMEM, row max
    float lmax = __int_as_float(0xff800000);  // -inf
    float4* xs4 = (float4*)xs;
    for (int k = tid; k < NV4; k += THREADS) {
        float4 v = xin[k];
        v.x *= 0.5f; v.y *= 0.5f; v.z *= 0.5f; v.w *= 0.5f;
        xs4[k] = v;
        lmax = fmaxf(lmax, fmaxf(fmaxf(v.x, v.y), fmaxf(v.z, v.w)));
    }
    lmax = warpMax(lmax);
    if (lane == 0) r.red[wid][0] = lmax;
    __syncthreads();
    if (wid == 0) {
        float m = r.red[lane][0];
        m = warpMax(m);
        if (lane == 0) r.bcast[0] = m;
    }
    __syncthreads();
    const float mx = r.bcast[0];

    float tau_lo = mx - 1.0f;
    float tau_hi = mx - 0.005590169943749474f;   // (1/32000)^(alpha-1) = sqrt(1/32000)

    // ---- Iteration 1: full-row fused 4-probe pass
    {
        float width = (tau_hi - tau_lo) / 5.0f;
        mass4_full(xs, tau_lo, width, &r, tid, lane, wid);
        update_tau(tau_lo, tau_hi, width, &r);
    }

    // ---- Compaction: elements with t <= tau_lo can never contribute again
    if (tid == 0) r.cnt = 0;
    __syncthreads();
    const float thr = tau_lo;
    for (int k = tid; k < NV4; k += THREADS) {
        float4 v = xs4[k];
        if (v.x > thr) { int p = atomicAdd(&r.cnt, 1); if (p < CCAP) cvals[p] = v.x; }
        if (v.y > thr) { int p = atomicAdd(&r.cnt, 1); if (p < CCAP) cvals[p] = v.y; }
        if (v.z > thr) { int p = atomicAdd(&r.cnt, 1); if (p < CCAP) cvals[p] = v.z; }
        if (v.w > thr) { int p = atomicAdd(&r.cnt, 1); if (p < CCAP) cvals[p] = v.w; }
    }
    __syncthreads();
    const int cnt = r.cnt;

    float Ssum;
    if (cnt <= CCAP) {
        // ---- Iterations 2..5 on the compact active set (tiny)
        for (int it = 0; it < 4; it++) {
            float width = (tau_hi - tau_lo) / 5.0f;
            const float t1 = tau_lo + 1.0f * width;
            const float t2 = tau_lo + 2.0f * width;
            const float t3 = tau_lo + 3.0f * width;
            const float t4 = tau_lo + 4.0f * width;
            float s0 = 0.f, s1 = 0.f, s2 = 0.f, s3 = 0.f;
            for (int k = tid; k < cnt; k += THREADS) {
                float c = cvals[k];
                float d0 = fmaxf(c - t1, 0.f); s0 = fmaf(d0, d0, s0);
                float d1 = fmaxf(c - t2, 0.f); s1 = fmaf(d1, d1, s1);
                float d2 = fmaxf(c - t3, 0.f); s2 = fmaf(d2, d2, s2);
                float d3 = fmaxf(c - t4, 0.f); s3 = fmaf(d3, d3, s3);
            }
            reduce4(s0, s1, s2, s3, &r, lane, wid);
            update_tau(tau_lo, tau_hi, width, &r);
        }
        // ---- Final normalizer from the compact set (p==0 off-list)
        float s = 0.f;
        for (int k = tid; k < cnt; k += THREADS) {
            float d0 = fmaxf(cvals[k] - tau_lo, 0.f);
            s = fmaf(d0, d0, s);
        }
        reduce4(s, 0.f, 0.f, 0.f, &r, lane, wid);
        Ssum = r.bcast[0];
    } else {
        // ---- Fallback (never expected for this data): full-row passes
        for (int it = 0; it < 4; it++) {
            float width = (tau_hi - tau_lo) / 5.0f;
            mass4_full(xs, tau_lo, width, &r, tid, lane, wid);
            update_tau(tau_lo, tau_hi, width, &r);
        }
        float s = 0.f;
        for (int k = tid; k < NV4; k += THREADS) {
            float4 v = xs4[k];
            float d0 = fmaxf(v.x - tau_lo, 0.f); s = fmaf(d0, d0, s);
            float d1 = fmaxf(v.y - tau_lo, 0.f); s = fmaf(d1, d1, s);
            float d2 = fmaxf(v.z - tau_lo, 0.f); s = fmaf(d2, d2, s);
            float d3 = fmaxf(v.w - tau_lo, 0.f); s = fmaf(d3, d3, s);
        }
        reduce4(s, 0.f, 0.f, 0.f, &r, lane, wid);
        Ssum = r.bcast[0];
    }

    const float invS = 1.0f / Ssum;
    const float tau  = tau_lo;

    // ---- Final write: p = relu(t - tau)^2 / S
    for (int k = tid; k < NV4; k += THREADS) {
        float4 v = xs4[k];
        float4 o;
        float d0 = fmaxf(v.x - tau, 0.f); o.x = d0 * d0 * invS;
        float d1 = fmaxf(v.y - tau, 0.f); o.y = d1 * d1 * invS;
        float d2 = fmaxf(v.z - tau, 0.f); o.z = d2 * d2 * invS;
        float d3 = fmaxf(v.w - tau, 0.f); o.w = d3 * d3 * invS;
        yout[k] = o;
    }
}

extern "C" void kernel_launch(void* const* d_in, const int* in_sizes, int n_in,
                              void* d_out, int out_size) {
    const float* X = (const float*)d_in[0];
    float* Y = (float*)d_out;
    const int rows = in_sizes[0] / D;   // 8192 for (4, 2048, 32000)
    cudaFuncSetAttribute(entmax_kernel,
                         cudaFuncAttributeMaxDynamicSharedMemorySize, SMEM_BYTES);
    entmax_kernel<<<rows, THREADS, SMEM_BYTES>>>(X, Y);
}

// round 4
// speedup vs baseline: 1.4211x; 1.4211x over previous
#include <cuda_runtime.h>

#define D        32000
#define NV4      (D / 4)
#define THREADS  512
#define NWARP    (THREADS / 32)
#define CCAP     4096

__device__ __forceinline__ float warpSum(float v) {
#pragma unroll
    for (int o = 16; o > 0; o >>= 1) v += __shfl_down_sync(0xffffffffu, v, o);
    return v;
}
__device__ __forceinline__ float warpMax(float v) {
#pragma unroll
    for (int o = 16; o > 0; o >>= 1) v = fmaxf(v, __shfl_down_sync(0xffffffffu, v, o));
    return v;
}

struct Red {
    float red[NWARP][4];
    float bcast[4];
    int   cnt;
};

// Block-reduce 4 partial sums; results broadcast via r->bcast[0..3].
__device__ void reduce4(float s0, float s1, float s2, float s3,
                        Red* r, int lane, int wid) {
    s0 = warpSum(s0); s1 = warpSum(s1); s2 = warpSum(s2); s3 = warpSum(s3);
    if (lane == 0) {
        r->red[wid][0] = s0; r->red[wid][1] = s1;
        r->red[wid][2] = s2; r->red[wid][3] = s3;
    }
    __syncthreads();
    if (wid == 0) {
        float a = (lane < NWARP) ? r->red[lane][0] : 0.f;
        float b = (lane < NWARP) ? r->red[lane][1] : 0.f;
        float c = (lane < NWARP) ? r->red[lane][2] : 0.f;
        float d = (lane < NWARP) ? r->red[lane][3] : 0.f;
        a = warpSum(a); b = warpSum(b); c = warpSum(c); d = warpSum(d);
        if (lane == 0) {
            r->bcast[0] = a; r->bcast[1] = b; r->bcast[2] = c; r->bcast[3] = d;
        }
    }
    __syncthreads();
}

__device__ __forceinline__ void update_tau(float& tau_lo, float& tau_hi,
                                           float width, const Red* r) {
    // j_best = largest j in 1..4 with mass >= 1 (reference semantics)
    int jb = 0;
    if (r->bcast[0] >= 1.0f) jb = 1;
    if (r->bcast[1] >= 1.0f) jb = 2;
    if (r->bcast[2] >= 1.0f) jb = 3;
    if (r->bcast[3] >= 1.0f) jb = 4;
    tau_lo = tau_lo + (float)jb * width;
    tau_hi = tau_lo + width;
}

__global__ __launch_bounds__(THREADS, 3)
void entmax_kernel(const float* __restrict__ X, float* __restrict__ Y) {
    __shared__ float cvals[CCAP];
    __shared__ int   cidx[CCAP];
    __shared__ Red   r;

    const int tid  = threadIdx.x;
    const int lane = tid & 31;
    const int wid  = tid >> 5;
    const size_t rowoff = (size_t)blockIdx.x * D;
    const float4* __restrict__ xin4 = (const float4*)(X + rowoff);
    float4* __restrict__       yout4 = (float4*)(Y + rowoff);

    // ---- Pass 1: stream row from HBM, row max (raw x; max(0.5x)=0.5*max(x))
    float lmax = __int_as_float(0xff800000);  // -inf
    for (int k = tid; k < NV4; k += THREADS) {
        float4 v = xin4[k];
        lmax = fmaxf(lmax, fmaxf(fmaxf(v.x, v.y), fmaxf(v.z, v.w)));
    }
    lmax = warpMax(lmax);
    if (lane == 0) r.red[wid][0] = lmax;
    if (tid == 0) r.cnt = 0;
    __syncthreads();
    if (wid == 0) {
        float m = (lane < NWARP) ? r.red[lane][0] : __int_as_float(0xff800000);
        m = warpMax(m);
        if (lane == 0) r.bcast[0] = m;
    }
    __syncthreads();
    const float mx = 0.5f * r.bcast[0];

    float tau_lo = mx - 1.0f;
    float tau_hi = mx - 0.005590169943749474f;   // (1/32000)^(alpha-1)

    // ---- Pass 2: stream row again (L2-hot), compact (val=0.5x, idx) for
    //      0.5x > tau_lo. Everything else contributes 0 to every probe mass,
    //      the normalizer, and the output (tau never decreases below tau_lo).
    const float thr2 = 2.0f * tau_lo;   // compare in raw-x units
    for (int k = tid; k < NV4; k += THREADS) {
        float4 v = __ldcs(&xin4[k]);
        float tv[4]; int ti[4]; int tcnt = 0;
        if (v.x > thr2) { tv[tcnt] = 0.5f * v.x; ti[tcnt] = 4 * k + 0; tcnt++; }
        if (v.y > thr2) { tv[tcnt] = 0.5f * v.y; ti[tcnt] = 4 * k + 1; tcnt++; }
        if (v.z > thr2) { tv[tcnt] = 0.5f * v.z; ti[tcnt] = 4 * k + 2; tcnt++; }
        if (v.w > thr2) { tv[tcnt] = 0.5f * v.w; ti[tcnt] = 4 * k + 3; tcnt++; }
        unsigned any = __ballot_sync(0xffffffffu, tcnt > 0);
        if (any) {
            // warp-aggregated append: inclusive scan of tcnt, one atomic per warp
            int off = tcnt;
#pragma unroll
            for (int d = 1; d < 32; d <<= 1) {
                int n = __shfl_up_sync(0xffffffffu, off, d);
                if (lane >= d) off += n;
            }
            int total = __shfl_sync(0xffffffffu, off, 31);
            int base;
            if (lane == 31) base = atomicAdd(&r.cnt, total);
            base = __shfl_sync(0xffffffffu, base, 31);
            int p = base + off - tcnt;
#pragma unroll
            for (int i = 0; i < 4; i++) {
                if (i < tcnt && p + i < CCAP) {
                    cvals[p + i] = tv[i];
                    cidx[p + i]  = ti[i];
                }
            }
        }
    }
    __syncthreads();
    const int cnt = r.cnt;

    if (cnt <= CCAP) {
        // ---- All 5 bisection iterations on the tiny compact set
        for (int it = 0; it < 5; it++) {
            float width = (tau_hi - tau_lo) / 5.0f;
            const float t1 = tau_lo + 1.0f * width;
            const float t2 = tau_lo + 2.0f * width;
            const float t3 = tau_lo + 3.0f * width;
            const float t4 = tau_lo + 4.0f * width;
            float s0 = 0.f, s1 = 0.f, s2 = 0.f, s3 = 0.f;
            for (int k = tid; k < cnt; k += THREADS) {
                float c = cvals[k];
                float d0 = fmaxf(c - t1, 0.f); s0 = fmaf(d0, d0, s0);
                float d1 = fmaxf(c - t2, 0.f); s1 = fmaf(d1, d1, s1);
                float d2 = fmaxf(c - t3, 0.f); s2 = fmaf(d2, d2, s2);
                float d3 = fmaxf(c - t4, 0.f); s3 = fmaf(d3, d3, s3);
            }
            reduce4(s0, s1, s2, s3, &r, lane, wid);
            update_tau(tau_lo, tau_hi, width, &r);
        }
        // ---- Normalizer from the compact set
        float s = 0.f;
        for (int k = tid; k < cnt; k += THREADS) {
            float d0 = fmaxf(cvals[k] - tau_lo, 0.f);
            s = fmaf(d0, d0, s);
        }
        reduce4(s, 0.f, 0.f, 0.f, &r, lane, wid);
        const float invS = 1.0f / r.bcast[0];
        const float tau  = tau_lo;

        // ---- Pass 3: zero-fill output (pure stores), then scatter nonzeros
        const float4 z4 = make_float4(0.f, 0.f, 0.f, 0.f);
        for (int k = tid; k < NV4; k += THREADS) __stcs(&yout4[k], z4);
        __syncthreads();
        float* __restrict__ yrow = (float*)(Y + rowoff);
        for (int k = tid; k < cnt; k += THREADS) {
            float d0 = fmaxf(cvals[k] - tau, 0.f);
            yrow[cidx[k]] = d0 * d0 * invS;
        }
    } else {
        // ---- Fallback (not expected for this data): full-row global passes
        for (int it = 0; it < 5; it++) {
            float width = (tau_hi - tau_lo) / 5.0f;
            const float t1 = tau_lo + 1.0f * width;
            const float t2 = tau_lo + 2.0f * width;
            const float t3 = tau_lo + 3.0f * width;
            const float t4 = tau_lo + 4.0f * width;
            float s0 = 0.f, s1 = 0.f, s2 = 0.f, s3 = 0.f;
            for (int k = tid; k < NV4; k += THREADS) {
                float4 v = xin4[k];
#define ACC(c)                                                        \
                {                                                     \
                    float cs = 0.5f * (c);                            \
                    float d0 = fmaxf(cs - t1, 0.f); s0 = fmaf(d0, d0, s0); \
                    float d1 = fmaxf(cs - t2, 0.f); s1 = fmaf(d1, d1, s1); \
                    float d2 = fmaxf(cs - t3, 0.f); s2 = fmaf(d2, d2, s2); \
                    float d3 = fmaxf(cs - t4, 0.f); s3 = fmaf(d3, d3, s3); \
                }
                ACC(v.x) ACC(v.y) ACC(v.z) ACC(v.w)
#undef ACC
            }
            reduce4(s0, s1, s2, s3, &r, lane, wid);
            update_tau(tau_lo, tau_hi, width, &r);
        }
        float s = 0.f;
        for (int k = tid; k < NV4; k += THREADS) {
            float4 v = xin4[k];
            float d0 = fmaxf(0.5f * v.x - tau_lo, 0.f); s = fmaf(d0, d0, s);
            float d1 = fmaxf(0.5f * v.y - tau_lo, 0.f); s = fmaf(d1, d1, s);
            float d2 = fmaxf(0.5f * v.z - tau_lo, 0.f); s = fmaf(d2, d2, s);
            float d3 = fmaxf(0.5f * v.w - tau_lo, 0.f); s = fmaf(d3, d3, s);
        }
        reduce4(s, 0.f, 0.f, 0.f, &r, lane, wid);
        const float invS = 1.0f / r.bcast[0];
        const float tau  = tau_lo;
        for (int k = tid; k < NV4; k += THREADS) {
            float4 v = xin4[k];
            float4 o;
            float d0 = fmaxf(0.5f * v.x - tau, 0.f); o.x = d0 * d0 * invS;
            float d1 = fmaxf(0.5f * v.y - tau, 0.f); o.y = d1 * d1 * invS;
            float d2 = fmaxf(0.5f * v.z - tau, 0.f); o.z = d2 * d2 * invS;
            float d3 = fmaxf(0.5f * v.w - tau, 0.f); o.w = d3 * d3 * invS;
            yout4[k] = o;
        }
    }
}

extern "C" void kernel_launch(void* const* d_in, const int* in_sizes, int n_in,
                              void* d_out, int out_size) {
    const float* X = (const float*)d_in[0];
    float* Y = (float*)d_out;
    const int rows = in_sizes[0] / D;   // 8192 for (4, 2048, 32000)
    entmax_kernel<<<rows, THREADS>>>(X, Y);
}

// round 6
// speedup vs baseline: 1.5702x; 1.1049x over previous
#include <cuda_runtime.h>

#define D        32000
#define NV4      (D / 4)
#define THREADS  512
#define NWARP    (THREADS / 32)
#define CCAP     4096
#define LBUF     12

__device__ __forceinline__ float warpSum(float v) {
#pragma unroll
    for (int o = 16; o > 0; o >>= 1) v += __shfl_down_sync(0xffffffffu, v, o);
    return v;
}
__device__ __forceinline__ float warpMax(float v) {
#pragma unroll
    for (int o = 16; o > 0; o >>= 1) v = fmaxf(v, __shfl_down_sync(0xffffffffu, v, o));
    return v;
}

struct Red {
    float red[NWARP][4];
    float bcast[4];
    int   warpTot[NWARP];
    int   warpBase[NWARP];
    int   cnt;
    int   ovf;
};

// Block-reduce 4 partial sums; results broadcast via r->bcast[0..3].
__device__ void reduce4(float s0, float s1, float s2, float s3,
                        Red* r, int lane, int wid) {
    s0 = warpSum(s0); s1 = warpSum(s1); s2 = warpSum(s2); s3 = warpSum(s3);
    if (lane == 0) {
        r->red[wid][0] = s0; r->red[wid][1] = s1;
        r->red[wid][2] = s2; r->red[wid][3] = s3;
    }
    __syncthreads();
    if (wid == 0) {
        float a = (lane < NWARP) ? r->red[lane][0] : 0.f;
        float b = (lane < NWARP) ? r->red[lane][1] : 0.f;
        float c = (lane < NWARP) ? r->red[lane][2] : 0.f;
        float d = (lane < NWARP) ? r->red[lane][3] : 0.f;
        a = warpSum(a); b = warpSum(b); c = warpSum(c); d = warpSum(d);
        if (lane == 0) {
            r->bcast[0] = a; r->bcast[1] = b; r->bcast[2] = c; r->bcast[3] = d;
        }
    }
    __syncthreads();
}

__device__ __forceinline__ void update_tau(float& tau_lo, float& tau_hi,
                                           float width, const Red* r) {
    // j_best = largest j in 1..4 with mass >= 1 (reference semantics)
    int jb = 0;
    if (r->bcast[0] >= 1.0f) jb = 1;
    if (r->bcast[1] >= 1.0f) jb = 2;
    if (r->bcast[2] >= 1.0f) jb = 3;
    if (r->bcast[3] >= 1.0f) jb = 4;
    tau_lo = tau_lo + (float)jb * width;
    tau_hi = tau_lo + width;
}

__global__ __launch_bounds__(THREADS, 3)
void entmax_kernel(const float* __restrict__ X, float* __restrict__ Y) {
    __shared__ float cvals[CCAP];
    __shared__ int   cidx[CCAP];
    __shared__ Red   r;

    const int tid  = threadIdx.x;
    const int lane = tid & 31;
    const int wid  = tid >> 5;
    const size_t rowoff = (size_t)blockIdx.x * D;
    const float4* __restrict__ xin4  = (const float4*)(X + rowoff);
    float4* __restrict__       yout4 = (float4*)(Y + rowoff);

    // ---- Pass 1: stream row from HBM, row max (raw x; max(0.5x)=0.5*max(x))
    float lmax = __int_as_float(0xff800000);  // -inf
    for (int k = tid; k < NV4; k += THREADS) {
        float4 v = xin4[k];
        lmax = fmaxf(lmax, fmaxf(fmaxf(v.x, v.y), fmaxf(v.z, v.w)));
    }
    lmax = warpMax(lmax);
    if (lane == 0) r.red[wid][0] = lmax;
    if (tid == 0) { r.cnt = 0; r.ovf = 0; }
    __syncthreads();
    if (wid == 0) {
        float m = (lane < NWARP) ? r.red[lane][0] : __int_as_float(0xff800000);
        m = warpMax(m);
        if (lane == 0) r.bcast[0] = m;
    }
    __syncthreads();
    const float mx = 0.5f * r.bcast[0];

    float tau_lo = mx - 1.0f;
    float tau_hi = mx - 0.005590169943749474f;   // (1/32000)^(alpha-1)

    // ---- Pass 2 (L2-hot re-read): per-thread buffered compaction of
    //      elements with 0.5x > tau_lo (all others contribute 0 to every
    //      probe mass, the normalizer, and the output since tau never
    //      decreases below tau_lo). Fused: zero-fill Y in the same loop.
    const float thr2 = 2.0f * tau_lo;   // compare in raw-x units
    float lv[LBUF];
    int   li[LBUF];
    int   myCnt = 0;
    const float4 z4 = make_float4(0.f, 0.f, 0.f, 0.f);
    for (int k = tid; k < NV4; k += THREADS) {
        float4 v = __ldcs(&xin4[k]);
        __stcs(&yout4[k], z4);
        // single guard: ~98% of float4s have no active element
        float m4 = fmaxf(fmaxf(v.x, v.y), fmaxf(v.z, v.w));
        if (m4 > thr2) {
            int k4 = 4 * k;
            if (v.x > thr2) { if (myCnt < LBUF) { lv[myCnt] = 0.5f * v.x; li[myCnt] = k4 + 0; myCnt++; } else r.ovf = 1; }
            if (v.y > thr2) { if (myCnt < LBUF) { lv[myCnt] = 0.5f * v.y; li[myCnt] = k4 + 1; myCnt++; } else r.ovf = 1; }
            if (v.z > thr2) { if (myCnt < LBUF) { lv[myCnt] = 0.5f * v.z; li[myCnt] = k4 + 2; myCnt++; } else r.ovf = 1; }
            if (v.w > thr2) { if (myCnt < LBUF) { lv[myCnt] = 0.5f * v.w; li[myCnt] = k4 + 3; myCnt++; } else r.ovf = 1; }
        }
    }

    // ---- One block-wide exclusive scan of per-thread counts.
    //      FULL-WARP participation everywhere (R5 deadlocked by entering a
    //      __shfl_up_sync(full mask) under `lane < NWARP`).
    {
        int inc = myCnt;
#pragma unroll
        for (int d = 1; d < 32; d <<= 1) {
            int n = __shfl_up_sync(0xffffffffu, inc, d);
            if (lane >= d) inc += n;
        }
        if (lane == 31) r.warpTot[wid] = inc;
        __syncthreads();
        if (wid == 0) {
            int v = (lane < NWARP) ? r.warpTot[lane] : 0;
            int s = v;
#pragma unroll
            for (int d = 1; d < 32; d <<= 1) {
                int n = __shfl_up_sync(0xffffffffu, s, d);
                if (lane >= d) s += n;
            }
            if (lane < NWARP) r.warpBase[lane] = s - v;
            if (lane == NWARP - 1) r.cnt = s;
        }
        __syncthreads();
        int base = r.warpBase[wid] + inc - myCnt;
        for (int i = 0; i < myCnt; i++) {
            int p = base + i;
            if (p < CCAP) { cvals[p] = lv[i]; cidx[p] = li[i]; }
        }
    }
    __syncthreads();
    const int cnt = r.cnt;

    if (cnt <= CCAP && !r.ovf) {
        // ---- All 5 bisection iterations on the tiny compact set
        for (int it = 0; it < 5; it++) {
            float width = (tau_hi - tau_lo) / 5.0f;
            const float t1 = tau_lo + 1.0f * width;
            const float t2 = tau_lo + 2.0f * width;
            const float t3 = tau_lo + 3.0f * width;
            const float t4 = tau_lo + 4.0f * width;
            float s0 = 0.f, s1 = 0.f, s2 = 0.f, s3 = 0.f;
            for (int k = tid; k < cnt; k += THREADS) {
                float c = cvals[k];
                float d0 = fmaxf(c - t1, 0.f); s0 = fmaf(d0, d0, s0);
                float d1 = fmaxf(c - t2, 0.f); s1 = fmaf(d1, d1, s1);
                float d2 = fmaxf(c - t3, 0.f); s2 = fmaf(d2, d2, s2);
                float d3 = fmaxf(c - t4, 0.f); s3 = fmaf(d3, d3, s3);
            }
            reduce4(s0, s1, s2, s3, &r, lane, wid);
            update_tau(tau_lo, tau_hi, width, &r);
        }
        // ---- Normalizer from the compact set
        float s = 0.f;
        for (int k = tid; k < cnt; k += THREADS) {
            float d0 = fmaxf(cvals[k] - tau_lo, 0.f);
            s = fmaf(d0, d0, s);
        }
        reduce4(s, 0.f, 0.f, 0.f, &r, lane, wid);
        const float invS = 1.0f / r.bcast[0];
        const float tau  = tau_lo;

        // ---- Scatter the few nonzeros (Y already zero-filled in pass 2;
        //      reduce4's __syncthreads ordered those CTA-local stores)
        float* __restrict__ yrow = (float*)(Y + rowoff);
        for (int k = tid; k < cnt; k += THREADS) {
            float d0 = fmaxf(cvals[k] - tau, 0.f);
            yrow[cidx[k]] = d0 * d0 * invS;
        }
    } else {
        // ---- Fallback (compact buffer overflow): full-row global passes
        for (int it = 0; it < 5; it++) {
            float width = (tau_hi - tau_lo) / 5.0f;
            const float t1 = tau_lo + 1.0f * width;
            const float t2 = tau_lo + 2.0f * width;
            const float t3 = tau_lo + 3.0f * width;
            const float t4 = tau_lo + 4.0f * width;
            float s0 = 0.f, s1 = 0.f, s2 = 0.f, s3 = 0.f;
            for (int k = tid; k < NV4; k += THREADS) {
                float4 v = xin4[k];
#define ACC(c)                                                        \
                {                                                     \
                    float cs = 0.5f * (c);                            \
                    float d0 = fmaxf(cs - t1, 0.f); s0 = fmaf(d0, d0, s0); \
                    float d1 = fmaxf(cs - t2, 0.f); s1 = fmaf(d1, d1, s1); \
                    float d2 = fmaxf(cs - t3, 0.f); s2 = fmaf(d2, d2, s2); \
                    float d3 = fmaxf(cs - t4, 0.f); s3 = fmaf(d3, d3, s3); \
                }
                ACC(v.x) ACC(v.y) ACC(v.z) ACC(v.w)
#undef ACC
            }
            reduce4(s0, s1, s2, s3, &r, lane, wid);
            update_tau(tau_lo, tau_hi, width, &r);
        }
        float s = 0.f;
        for (int k = tid; k < NV4; k += THREADS) {
            float4 v = xin4[k];
            float d0 = fmaxf(0.5f * v.x - tau_lo, 0.f); s = fmaf(d0, d0, s);
            float d1 = fmaxf(0.5f * v.y - tau_lo, 0.f); s = fmaf(d1, d1, s);
            float d2 = fmaxf(0.5f * v.z - tau_lo, 0.f); s = fmaf(d2, d2, s);
            float d3 = fmaxf(0.5f * v.w - tau_lo, 0.f); s = fmaf(d3, d3, s);
        }
        reduce4(s, 0.f, 0.f, 0.f, &r, lane, wid);
        const float invS = 1.0f / r.bcast[0];
        const float tau  = tau_lo;
        for (int k = tid; k < NV4; k += THREADS) {
            float4 v = xin4[k];
            float4 o;
            float d0 = fmaxf(0.5f * v.x - tau, 0.f); o.x = d0 * d0 * invS;
            float d1 = fmaxf(0.5f * v.y - tau, 0.f); o.y = d1 * d1 * invS;
            float d2 = fmaxf(0.5f * v.z - tau, 0.f); o.z = d2 * d2 * invS;
            float d3 = fmaxf(0.5f * v.w - tau, 0.f); o.w = d3 * d3 * invS;
            yout4[k] = o;
        }
    }
}

extern "C" void kernel_launch(void* const* d_in, const int* in_sizes, int n_in,
                              void* d_out, int out_size) {
    const float* X = (const float*)d_in[0];
    float* Y = (float*)d_out;
    const int rows = in_sizes[0] / D;   // 8192 for (4, 2048, 32000)
    entmax_kernel<<<rows, THREADS>>>(X, Y);
}